// round 12
// baseline (speedup 1.0000x reference)
#include <cuda_runtime.h>

#define Bn  2
#define Cn  3
#define OCn 2
#define Hn  96
#define Wn  96
#define Nn  (Hn*Wn)        // 9216
#define NPER (Bn*Nn)       // 18432

// Scratch — fully overwritten every replay; no atomics, no counters.
__device__ float g_Spart[18][4];          // per-(pair,chunk) dot partials (scaled)
__device__ float g_part[4][72];           // BN stat partials per k2 block
__device__ float g_y[Bn*OCn*Nn];          // conv output

// ---------------------------------------------------------------------------
// K1: 72 CTAs. pair = (b,ch,c) in [0,18), chunk in [0,4). 576 float4 per chunk.
// ---------------------------------------------------------------------------
__global__ void __launch_bounds__(256)
k1_dots(const float* __restrict__ q, const float* __restrict__ k)
{
    const int bk    = blockIdx.x;
    const int pair  = bk >> 2;
    const int chunk = bk & 3;
    const int b     = pair / 9;
    const int rem   = pair % 9;                 // ch*3 + c
    const float4* kr = (const float4*)(k + (b*Cn + rem/3)*Nn) + chunk*576;
    const float4* qr = (const float4*)(q + (b*Cn + rem%3)*Nn) + chunk*576;
    const int t = threadIdx.x;

    // 576 = 2*256 + 64
    float acc;
    {
        const float4 a0 = kr[t],       b0 = qr[t];
        const float4 a1 = kr[t + 256], b1 = qr[t + 256];
        acc  = a0.x*b0.x + a0.y*b0.y + a0.z*b0.z + a0.w*b0.w;
        acc += a1.x*b1.x + a1.y*b1.y + a1.z*b1.z + a1.w*b1.w;
        if (t < 64) {
            const float4 a2 = kr[t + 512], b2 = qr[t + 512];
            acc += a2.x*b2.x + a2.y*b2.y + a2.z*b2.z + a2.w*b2.w;
        }
    }

    __shared__ float sm[8];
    const int lane = t & 31, warp = t >> 5;
    #pragma unroll
    for (int o = 16; o; o >>= 1) acc += __shfl_down_sync(0xffffffffu, acc, o);
    if (lane == 0) sm[warp] = acc;
    __syncthreads();
    if (warp == 0) {
        acc = (lane < 8) ? sm[lane] : 0.f;
        #pragma unroll
        for (int o = 4; o; o >>= 1) acc += __shfl_down_sync(0xffffffffu, acc, o);
        if (lane == 0)
            g_Spart[pair][chunk] = acc * 0.57735026918962576451f;  // 1/sqrt(3)
    }
}

// ---------------------------------------------------------------------------
// K2: 72 CTAs x 256, one pixel/thread. Fold S into effective weights per block
// (54 FMA redundant), conv = 27 L2-hot loads + 54 FMA per pixel. Writes y and
// per-block BN stat partials (deterministic, no atomics).
// ---------------------------------------------------------------------------
__global__ void __launch_bounds__(256)
k2_conv(const float* __restrict__ q, const float* __restrict__ w,
        const float* __restrict__ bias)
{
    __shared__ float sWp[OCn][Cn][9];        // S-folded effective weights
    __shared__ float red[4][8];

    const int t   = threadIdx.x;
    const int bk  = blockIdx.x;
    const int idx = bk * 256 + t;            // 0..18431
    const int b   = idx / Nn;
    const int n   = idx - b * Nn;
    const int yy  = n / Wn, xx = n - yy * Wn;

    // Fold: w'[o][ch][kk] = sum_c S[ch][c] * w[o][c][kk]
    if (t < OCn*Cn*9) {                      // 54 threads
        const int o   = t / 27;
        const int rem = t % 27;
        const int ch  = rem / 9;
        const int kk  = rem % 9;
        float acc = 0.f;
        #pragma unroll
        for (int c = 0; c < 3; c++) {
            const int j = ch*3 + c;
            const float S = g_Spart[b*9 + j][0] + g_Spart[b*9 + j][1]
                          + g_Spart[b*9 + j][2] + g_Spart[b*9 + j][3];
            acc += S * w[(o*Cn + c)*9 + kk];
        }
        sWp[o][ch][kk] = acc;
    }
    __syncthreads();

    float acc0 = bias[0];
    float acc1 = bias[1];
    const float* qb = q + b*Cn*Nn;

    #pragma unroll
    for (int ky = 0; ky < 3; ky++) {
        const int iy = yy + ky - 1;
        #pragma unroll
        for (int kx = 0; kx < 3; kx++) {
            const int ix = xx + kx - 1;
            if (iy >= 0 && iy < Hn && ix >= 0 && ix < Wn) {
                const int m  = iy * Wn + ix;
                const int kk = ky*3 + kx;
                const float q0 = qb[0*Nn + m];
                const float q1 = qb[1*Nn + m];
                const float q2 = qb[2*Nn + m];
                acc0 += sWp[0][0][kk]*q0 + sWp[0][1][kk]*q1 + sWp[0][2][kk]*q2;
                acc1 += sWp[1][0][kk]*q0 + sWp[1][1][kk]*q1 + sWp[1][2][kk]*q2;
            }
        }
    }

    g_y[(b*OCn + 0)*Nn + n] = acc0;
    g_y[(b*OCn + 1)*Nn + n] = acc1;

    // Block-reduce the 4 BN stat partials -> g_part[*][bk]
    float s0 = acc0, s1 = acc1, s2 = acc0*acc0, s3 = acc1*acc1;
    const int lane = t & 31, warp = t >> 5;
    #pragma unroll
    for (int o = 16; o; o >>= 1) {
        s0 += __shfl_down_sync(0xffffffffu, s0, o);
        s1 += __shfl_down_sync(0xffffffffu, s1, o);
        s2 += __shfl_down_sync(0xffffffffu, s2, o);
        s3 += __shfl_down_sync(0xffffffffu, s3, o);
    }
    if (lane == 0) { red[0][warp]=s0; red[1][warp]=s1; red[2][warp]=s2; red[3][warp]=s3; }
    __syncthreads();
    if (warp == 0 && lane < 4) {
        float r = 0.f;
        #pragma unroll
        for (int j = 0; j < 8; j++) r += red[lane][j];
        g_part[lane][bk] = r;
    }
}

// ---------------------------------------------------------------------------
// K3: 36 CTAs x 256, one float4/thread. Each block redundantly reduces the
// 4x72 stat partials (L2-hot), then BN + affine + LeakyReLU(0.1).
// ---------------------------------------------------------------------------
__global__ void __launch_bounds__(256)
k3_bn(const float* __restrict__ gamma, const float* __restrict__ beta,
      float* __restrict__ out)
{
    __shared__ float sstat[4];
    const int t = threadIdx.x;
    const int lane = t & 31, warp = t >> 5;

    if (warp < 4) {
        float v = g_part[warp][lane] + g_part[warp][lane + 32]
                + ((lane < 8) ? g_part[warp][lane + 64] : 0.f);
        #pragma unroll
        for (int o = 16; o; o >>= 1) v += __shfl_down_sync(0xffffffffu, v, o);
        if (lane == 0) sstat[warp] = v;
    }
    __syncthreads();

    const float inv_n = 1.0f / (float)NPER;
    const float mean0 = sstat[0] * inv_n;
    const float mean1 = sstat[1] * inv_n;
    const float var0  = sstat[2] * inv_n - mean0*mean0;
    const float var1  = sstat[3] * inv_n - mean1*mean1;
    const float sc0   = rsqrtf(var0 + 1e-5f) * gamma[0];
    const float sc1   = rsqrtf(var1 + 1e-5f) * gamma[1];
    const float be0   = beta[0], be1 = beta[1];

    const int i4 = blockIdx.x * 256 + t;       // 0..9215 float4s
    const int c  = (i4 / 2304) & 1;            // plane = 2304 float4; [b][oc][n]
    const float mean = c ? mean1 : mean0;
    const float sc   = c ? sc1   : sc0;
    const float be   = c ? be1   : be0;

    float4 y = ((const float4*)g_y)[i4];
    float4 r;
    r.x = (y.x - mean) * sc + be; r.x = (r.x >= 0.f) ? r.x : 0.1f*r.x;
    r.y = (y.y - mean) * sc + be; r.y = (r.y >= 0.f) ? r.y : 0.1f*r.y;
    r.z = (y.z - mean) * sc + be; r.z = (r.z >= 0.f) ? r.z : 0.1f*r.z;
    r.w = (y.w - mean) * sc + be; r.w = (r.w >= 0.f) ? r.w : 0.1f*r.w;
    ((float4*)out)[i4] = r;
}

// ---------------------------------------------------------------------------
extern "C" void kernel_launch(void* const* d_in, const int* in_sizes, int n_in,
                              void* d_out, int out_size)
{
    const float* q      = (const float*)d_in[0];  // X_tnext
    const float* k      = (const float*)d_in[1];  // X_hat_tnext
    const float* conv_w = (const float*)d_in[2];
    const float* conv_b = (const float*)d_in[3];
    const float* gamma  = (const float*)d_in[4];
    const float* beta   = (const float*)d_in[5];
    float* out = (float*)d_out;

    k1_dots<<<72, 256>>>(q, k);
    k2_conv<<<72, 256>>>(q, conv_w, conv_b);
    k3_bn<<<36, 256>>>(gamma, beta, out);
}

// round 13
// speedup vs baseline: 1.0238x; 1.0238x over previous
#include <cuda_runtime.h>
#include <cstdint>

#define Bn  2
#define Cn  3
#define OCn 2
#define Hn  96
#define Wn  96
#define Nn  (Hn*Wn)        // 9216
#define NPER (Bn*Nn)       // 18432
#define NCTA 8             // plain CTAs, no cluster
#define NT   768           // 24 warps
#define ROWS 24            // rows per CTA (4 CTAs per batch)

// Cross-CTA scratch. Epoch counters only grow -> replay-safe with no resets.
__device__ float g_Sp[NCTA][9];    // per-CTA dot partials
__device__ float g_bnp[NCTA][4];   // per-CTA BN partials
__device__ int   g_ep1[NCTA];      // epoch flags for S exchange
__device__ int   g_ep2[NCTA];      // epoch flags for BN exchange

__device__ __forceinline__ int ldcv_i(const int* p) {
    int v; asm volatile("ld.global.cv.s32 %0, [%1];" : "=r"(v) : "l"(p)); return v;
}
__device__ __forceinline__ float ldcv_f(const float* p) {
    float v; asm volatile("ld.global.cv.f32 %0, [%1];" : "=f"(v) : "l"(p)); return v;
}

__global__ void __launch_bounds__(NT, 1)
fused_spin(const float* __restrict__ q, const float* __restrict__ k,
           const float* __restrict__ w, const float* __restrict__ bias,
           const float* __restrict__ gamma, const float* __restrict__ beta,
           float* __restrict__ out)
{
    __shared__ __align__(16) float sq[Cn][ROWS+2][Wn];  // ~30KB tile + halo
    __shared__ float dmat[144][9];     // dot partials (18 warps x 8 lanes)
    __shared__ float bnmat[192][5];    // BN partials (24 warps x 8 lanes)
    __shared__ float sw[54];           // raw conv weights (prefetched)
    __shared__ float sWp[OCn][Cn][9];  // S-folded effective conv weights
    __shared__ float sc[6];            // bias0,bias1,g0,g1,be0,be1
    __shared__ float sstat[4];

    const int t    = threadIdx.x;
    const int bk   = blockIdx.x;
    const int lane = t & 31, warp = t >> 5;
    const int b    = bk >> 2;
    const int r0   = (bk & 3) * ROWS;
    const float* qb = q + b*Cn*Nn;
    const float* kb = k + b*Cn*Nn;

    // ================= Phase 1: ONE parallel load wave ====================
    float4 qq[3], kk[3];
    const int rr = t / 24, c4 = t % 24;
    if (t < 576) {
        #pragma unroll
        for (int ch = 0; ch < 3; ch++) {
            qq[ch] = ((const float4*)(qb + ch*Nn + (r0+rr)*Wn))[c4];
            kk[ch] = ((const float4*)(kb + ch*Nn + (r0+rr)*Wn))[c4];
        }
        #pragma unroll
        for (int ch = 0; ch < 3; ch++)
            ((float4*)&sq[ch][rr+1][0])[c4] = qq[ch];
    } else {
        const int i = t - 576;             // 0..191
        if (i < 144) {
            const int ch    = i / 48;
            const int which = (i % 48) / 24;   // 0=top halo, 1=bottom halo
            const int hc4   = i % 24;
            const int grow  = r0 - 1 + which*(ROWS+1);
            float4 v = make_float4(0.f, 0.f, 0.f, 0.f);
            if (grow >= 0 && grow < Hn)
                v = ((const float4*)(qb + ch*Nn + grow*Wn))[hc4];
            ((float4*)&sq[ch][which*(ROWS+1)][0])[hc4] = v;
        }
        if (i < 54) sw[i] = w[i];
        else if (i >= 54 && i < 60) {
            const int j = i - 54;
            sc[j] = (j < 2) ? bias[j] : (j < 4 ? gamma[j-2] : beta[j-4]);
        }
    }

    // ---- dots from registers ----
    if (t < 576) {
        float d[9];
        #pragma unroll
        for (int ch = 0; ch < 3; ch++)
            #pragma unroll
            for (int c = 0; c < 3; c++)
                d[ch*3+c] = kk[ch].x*qq[c].x + kk[ch].y*qq[c].y
                          + kk[ch].z*qq[c].z + kk[ch].w*qq[c].w;
        #pragma unroll
        for (int j = 0; j < 9; j++) {
            d[j] += __shfl_down_sync(0xffffffffu, d[j], 16);
            d[j] += __shfl_down_sync(0xffffffffu, d[j], 8);
        }
        if (lane < 8) {
            #pragma unroll
            for (int j = 0; j < 9; j++) dmat[warp*8 + lane][j] = d[j];
        }
    }
    __syncthreads();

    if (warp < 9) {
        float v = 0.f;
        #pragma unroll
        for (int i = 0; i < 5; i++) {
            const int row = lane + 32*i;
            if (row < 144) v += dmat[row][warp];
        }
        #pragma unroll
        for (int o = 16; o; o >>= 1) v += __shfl_down_sync(0xffffffffu, v, o);
        if (lane == 0) g_Sp[bk][warp] = v;
    }

    // ---- Sync 1: within my batch's 4 CTAs (epoch spin) ----
    __syncthreads();
    __threadfence();
    if (t == 0) {
        const int e = g_ep1[bk] + 1;           // sole writer of own slot
        *(volatile int*)&g_ep1[bk] = e;
        #pragma unroll
        for (int j = 0; j < 4; j++) {
            const int peer = b*4 + j;
            if (peer != bk) while (ldcv_i(&g_ep1[peer]) < e) { }
        }
        __threadfence();
    }
    __syncthreads();

    // ---- Fold S into effective conv weights ----
    if (t < OCn*Cn*9) {                 // 54 threads
        const int o   = t / 27;
        const int rem = t % 27;
        const int ch  = rem / 9;
        const int kkk = rem % 9;
        float acc = 0.f;
        #pragma unroll
        for (int c = 0; c < 3; c++) {
            const int j = ch*3 + c;
            const float S = (ldcv_f(&g_Sp[b*4+0][j]) + ldcv_f(&g_Sp[b*4+1][j])
                           + ldcv_f(&g_Sp[b*4+2][j]) + ldcv_f(&g_Sp[b*4+3][j]))
                          * 0.57735026918962576451f;   // 1/sqrt(3)
            acc += S * sw[(o*Cn + c)*9 + kkk];
        }
        sWp[o][ch][kkk] = acc;
    }
    __syncthreads();

    // ---- Phase 2: conv from smem tile; 3 contiguous pixels per thread ----
    const int row = t >> 5;
    const int col = (t & 31) * 3;
    const float bias0 = sc[0], bias1 = sc[1];
    float y0[3] = {bias0, bias0, bias0};
    float y1[3] = {bias1, bias1, bias1};

    #pragma unroll
    for (int tr = 0; tr < 3; tr++) {
        const int trow = row + tr;
        #pragma unroll
        for (int ch = 0; ch < 3; ch++) {
            float v[5];
            v[0] = (col == 0)  ? 0.f : sq[ch][trow][col-1];
            v[1] = sq[ch][trow][col+0];
            v[2] = sq[ch][trow][col+1];
            v[3] = sq[ch][trow][col+2];
            v[4] = (col == 93) ? 0.f : sq[ch][trow][col+3];
            #pragma unroll
            for (int tc = 0; tc < 3; tc++) {
                const float w0 = sWp[0][ch][tr*3+tc];
                const float w1 = sWp[1][ch][tr*3+tc];
                #pragma unroll
                for (int j = 0; j < 3; j++) {
                    y0[j] += w0 * v[j+tc];
                    y1[j] += w1 * v[j+tc];
                }
            }
        }
    }

    // ---- BN partials via transpose-reduce ----
    {
        float s[4] = { y0[0]+y0[1]+y0[2],
                       y1[0]+y1[1]+y1[2],
                       y0[0]*y0[0]+y0[1]*y0[1]+y0[2]*y0[2],
                       y1[0]*y1[0]+y1[1]*y1[1]+y1[2]*y1[2] };
        #pragma unroll
        for (int j = 0; j < 4; j++) {
            s[j] += __shfl_down_sync(0xffffffffu, s[j], 16);
            s[j] += __shfl_down_sync(0xffffffffu, s[j], 8);
        }
        if (lane < 8) {
            #pragma unroll
            for (int j = 0; j < 4; j++) bnmat[warp*8 + lane][j] = s[j];
        }
    }
    __syncthreads();
    if (warp < 4) {
        float v = 0.f;
        #pragma unroll
        for (int i = 0; i < 6; i++) v += bnmat[lane + 32*i][warp];
        #pragma unroll
        for (int o = 16; o; o >>= 1) v += __shfl_down_sync(0xffffffffu, v, o);
        if (lane == 0) g_bnp[bk][warp] = v;
    }

    // ---- Sync 2: all 8 CTAs (epoch spin) ----
    __syncthreads();
    __threadfence();
    if (t == 0) {
        const int e = g_ep2[bk] + 1;
        *(volatile int*)&g_ep2[bk] = e;
        #pragma unroll
        for (int peer = 0; peer < NCTA; peer++) {
            if (peer != bk) while (ldcv_i(&g_ep2[peer]) < e) { }
        }
        __threadfence();
    }
    __syncthreads();

    if (t < 4) {
        float v = 0.f;
        #pragma unroll
        for (int rk = 0; rk < NCTA; rk++) v += ldcv_f(&g_bnp[rk][t]);
        sstat[t] = v;
    }
    __syncthreads();

    // ---- Phase 3: BN + affine + LeakyReLU(0.1) ----
    const float inv_n = 1.0f / (float)NPER;
    const float mean0 = sstat[0] * inv_n;
    const float mean1 = sstat[1] * inv_n;
    const float var0  = sstat[2] * inv_n - mean0*mean0;
    const float var1  = sstat[3] * inv_n - mean1*mean1;
    const float sc0   = rsqrtf(var0 + 1e-5f) * sc[2];
    const float sc1   = rsqrtf(var1 + 1e-5f) * sc[3];
    const float be0   = sc[4], be1 = sc[5];

    float* o0 = out + (b*OCn + 0)*Nn + (r0 + row)*Wn + col;
    float* o1 = out + (b*OCn + 1)*Nn + (r0 + row)*Wn + col;
    #pragma unroll
    for (int j = 0; j < 3; j++) {
        float v0 = (y0[j] - mean0) * sc0 + be0;
        float v1 = (y1[j] - mean1) * sc1 + be1;
        o0[j] = (v0 >= 0.f) ? v0 : 0.1f*v0;
        o1[j] = (v1 >= 0.f) ? v1 : 0.1f*v1;
    }
}

// ---------------------------------------------------------------------------
extern "C" void kernel_launch(void* const* d_in, const int* in_sizes, int n_in,
                              void* d_out, int out_size)
{
    const float* q      = (const float*)d_in[0];  // X_tnext
    const float* k      = (const float*)d_in[1];  // X_hat_tnext
    const float* conv_w = (const float*)d_in[2];
    const float* conv_b = (const float*)d_in[3];
    const float* gamma  = (const float*)d_in[4];
    const float* beta   = (const float*)d_in[5];
    float* out = (float*)d_out;

    fused_spin<<<NCTA, NT>>>(q, k, conv_w, conv_b, gamma, beta, out);
}

// round 14
// speedup vs baseline: 1.1505x; 1.1237x over previous
#include <cuda_runtime.h>
#include <cstdint>

#define Bn  2
#define Cn  3
#define OCn 2
#define Hn  96
#define Wn  96
#define Nn  (Hn*Wn)        // 9216
#define NPER (Bn*Nn)       // 18432
#define NCTA 16            // total CTAs = 2 clusters of 8
#define CLU  8             // cluster size = one batch
#define NT   576           // 18 warps
#define ROWS 12            // rows per CTA (8 CTAs per batch)

// Cross-CTA scratch. Epoch counters only grow -> replay-safe, no resets.
__device__ float g_bnp[NCTA][4];   // per-CTA BN partials
__device__ int   g_ep[NCTA];       // epoch flags for BN exchange

__device__ __forceinline__ uint32_t s2u(const void* p) {
    uint32_t a;
    asm("{ .reg .u64 t; cvta.to.shared.u64 t, %1; cvt.u32.u64 %0, t; }"
        : "=r"(a) : "l"(p));
    return a;
}
__device__ __forceinline__ void st_peer(uint32_t saddr, int rank, float v) {
    uint32_t r;
    asm volatile("mapa.shared::cluster.u32 %0, %1, %2;" : "=r"(r) : "r"(saddr), "r"(rank));
    asm volatile("st.shared::cluster.f32 [%0], %1;" :: "r"(r), "f"(v) : "memory");
}
__device__ __forceinline__ int ldcv_i(const int* p) {
    int v; asm volatile("ld.global.cv.s32 %0, [%1];" : "=r"(v) : "l"(p)); return v;
}
__device__ __forceinline__ float ldcv_f(const float* p) {
    float v; asm volatile("ld.global.cv.f32 %0, [%1];" : "=f"(v) : "l"(p)); return v;
}
#define CLUSTER_ARRIVE() asm volatile("barrier.cluster.arrive.aligned;" ::: "memory")
#define CLUSTER_WAIT()   asm volatile("barrier.cluster.wait.aligned;"   ::: "memory")

__global__ void __launch_bounds__(NT, 1) __cluster_dims__(CLU, 1, 1)
fused_2clu(const float* __restrict__ q, const float* __restrict__ k,
           const float* __restrict__ w, const float* __restrict__ bias,
           const float* __restrict__ gamma, const float* __restrict__ beta,
           float* __restrict__ out)
{
    __shared__ __align__(16) float sq[Cn][ROWS+2][Wn];  // ~16KB tile + halo
    __shared__ float dmat[72][9];      // dot partials (9 warps x 8 lanes)
    __shared__ float bnmat[144][5];    // BN partials (18 warps x 8 lanes)
    __shared__ float peerS[CLU][9];    // DSMEM: written remotely by cluster peers
    __shared__ float sw[54];           // raw conv weights
    __shared__ float sWp[OCn][Cn][9];  // S-folded effective conv weights
    __shared__ float sc[6];            // bias0,bias1,g0,g1,be0,be1
    __shared__ float sstat[4];

    const int t    = threadIdx.x;
    const int bk   = blockIdx.x;       // 0..15
    const int lane = t & 31, warp = t >> 5;
    const int b    = bk >> 3;          // batch = cluster id
    const int crk  = bk & 7;           // cluster rank
    const int r0   = crk * ROWS;       // first owned image row
    const float* qb = q + b*Cn*Nn;
    const float* kb = k + b*Cn*Nn;

    // ================= Phase 1: ONE parallel load wave ====================
    // t<288: 3 q-float4 (owned rows -> regs + smem) + 3 k-float4 (regs)
    // t 288..431: halo rows (2 x 3ch x 24 f4 = 144); t 288..347: weights/params
    float4 qq[3], kk[3];
    const int rr = t / 24, c4 = t % 24;        // rr 0..11 for t<288
    if (t < 288) {
        #pragma unroll
        for (int ch = 0; ch < 3; ch++) {
            qq[ch] = ((const float4*)(qb + ch*Nn + (r0+rr)*Wn))[c4];
            kk[ch] = ((const float4*)(kb + ch*Nn + (r0+rr)*Wn))[c4];
        }
        #pragma unroll
        for (int ch = 0; ch < 3; ch++)
            ((float4*)&sq[ch][rr+1][0])[c4] = qq[ch];
    } else {
        const int i = t - 288;                 // 0..287
        if (i < 144) {
            const int ch    = i / 48;
            const int which = (i % 48) / 24;   // 0=top halo, 1=bottom halo
            const int hc4   = i % 24;
            const int grow  = r0 - 1 + which*(ROWS+1);
            float4 v = make_float4(0.f, 0.f, 0.f, 0.f);
            if (grow >= 0 && grow < Hn)
                v = ((const float4*)(qb + ch*Nn + grow*Wn))[hc4];
            ((float4*)&sq[ch][which*(ROWS+1)][0])[hc4] = v;
        } else if (i < 198) {
            sw[i - 144] = w[i - 144];
        } else if (i < 204) {
            const int j = i - 198;
            sc[j] = (j < 2) ? bias[j] : (j < 4 ? gamma[j-2] : beta[j-4]);
        }
    }

    // ---- dots from registers (warps 0-8) ----
    if (t < 288) {
        float d[9];
        #pragma unroll
        for (int ch = 0; ch < 3; ch++)
            #pragma unroll
            for (int c = 0; c < 3; c++)
                d[ch*3+c] = kk[ch].x*qq[c].x + kk[ch].y*qq[c].y
                          + kk[ch].z*qq[c].z + kk[ch].w*qq[c].w;
        #pragma unroll
        for (int j = 0; j < 9; j++) {
            d[j] += __shfl_down_sync(0xffffffffu, d[j], 16);
            d[j] += __shfl_down_sync(0xffffffffu, d[j], 8);
        }
        if (lane < 8) {
            #pragma unroll
            for (int j = 0; j < 9; j++) dmat[warp*8 + lane][j] = d[j];
        }
    }
    __syncthreads();

    // 9 warps: column sums over 72 rows, then DSMEM broadcast to cluster
    if (warp < 9) {
        float v = dmat[lane][warp] + dmat[lane + 32][warp]
                + ((lane < 8) ? dmat[lane + 64][warp] : 0.f);
        #pragma unroll
        for (int o = 16; o; o >>= 1) v += __shfl_down_sync(0xffffffffu, v, o);
        if (lane == 0) {
            const uint32_t a = s2u(&peerS[crk][warp]);
            #pragma unroll
            for (int rk = 0; rk < CLU; rk++) st_peer(a, rk, v);
        }
    }

    // ---- Cluster barrier (release/acquire): S partials visible in-batch ----
    CLUSTER_ARRIVE();
    CLUSTER_WAIT();

    // ---- Fold S into effective conv weights ----
    if (t < OCn*Cn*9) {                 // 54 threads
        const int o   = t / 27;
        const int rem = t % 27;
        const int ch  = rem / 9;
        const int kkk = rem % 9;
        float acc = 0.f;
        #pragma unroll
        for (int c = 0; c < 3; c++) {
            const int j = ch*3 + c;
            float S = 0.f;
            #pragma unroll
            for (int rk = 0; rk < CLU; rk++) S += peerS[rk][j];
            acc += S * 0.57735026918962576451f * sw[(o*Cn + c)*9 + kkk];
        }
        sWp[o][ch][kkk] = acc;
    }
    __syncthreads();

    // ---- Phase 2: conv; 2 pixels per thread (col, col+48) ----
    const int row  = t / 48;           // 0..11
    const int cidx = t % 48;
    const int colA = cidx, colB = cidx + 48;
    const float bias0 = sc[0], bias1 = sc[1];
    float y0[2] = {bias0, bias0};      // [pixel]
    float y1[2] = {bias1, bias1};

    #pragma unroll
    for (int tr = 0; tr < 3; tr++) {
        const int trow = row + tr;
        #pragma unroll
        for (int ch = 0; ch < 3; ch++) {
            float vA[3], vB[3];
            vA[0] = (colA == 0)  ? 0.f : sq[ch][trow][colA-1];
            vA[1] = sq[ch][trow][colA];
            vA[2] = sq[ch][trow][colA+1];
            vB[0] = sq[ch][trow][colB-1];
            vB[1] = sq[ch][trow][colB];
            vB[2] = (colB == 95) ? 0.f : sq[ch][trow][colB+1];
            #pragma unroll
            for (int tc = 0; tc < 3; tc++) {
                const float w0 = sWp[0][ch][tr*3+tc];
                const float w1 = sWp[1][ch][tr*3+tc];
                y0[0] += w0 * vA[tc];  y1[0] += w1 * vA[tc];
                y0[1] += w0 * vB[tc];  y1[1] += w1 * vB[tc];
            }
        }
    }

    // ---- BN partials via transpose-reduce ----
    {
        float s[4] = { y0[0]+y0[1], y1[0]+y1[1],
                       y0[0]*y0[0]+y0[1]*y0[1],
                       y1[0]*y1[0]+y1[1]*y1[1] };
        #pragma unroll
        for (int j = 0; j < 4; j++) {
            s[j] += __shfl_down_sync(0xffffffffu, s[j], 16);
            s[j] += __shfl_down_sync(0xffffffffu, s[j], 8);
        }
        if (lane < 8) {
            #pragma unroll
            for (int j = 0; j < 4; j++) bnmat[warp*8 + lane][j] = s[j];
        }
    }
    __syncthreads();
    if (warp < 4) {
        float v = bnmat[lane][warp] + bnmat[lane+32][warp]
                + bnmat[lane+64][warp] + bnmat[lane+96][warp]
                + ((lane < 16) ? bnmat[lane+128][warp] : 0.f);
        #pragma unroll
        for (int o = 16; o; o >>= 1) v += __shfl_down_sync(0xffffffffu, v, o);
        if (lane == 0) g_bnp[bk][warp] = v;
    }

    // ---- Global sync over 16 CTAs: epoch spin with PARALLEL polling ----
    int e = 0;
    if (t < NCTA) e = ldcv_i(&g_ep[bk]) + 1;   // read before anyone publishes
    __syncthreads();
    __threadfence();
    if (t == 0) *(volatile int*)&g_ep[bk] = e;
    if (t < NCTA && t != bk) {
        while (ldcv_i(&g_ep[t]) < e) { }
    }
    __threadfence();
    __syncthreads();

    if (t < 4) {
        float v = 0.f;
        #pragma unroll
        for (int rk = 0; rk < NCTA; rk++) v += ldcv_f(&g_bnp[rk][t]);
        sstat[t] = v;
    }
    __syncthreads();

    // ---- Phase 3: BN (biased var, eps=1e-5) + affine + LeakyReLU(0.1) ----
    const float inv_n = 1.0f / (float)NPER;
    const float mean0 = sstat[0] * inv_n;
    const float mean1 = sstat[1] * inv_n;
    const float var0  = sstat[2] * inv_n - mean0*mean0;
    const float var1  = sstat[3] * inv_n - mean1*mean1;
    const float sc0   = rsqrtf(var0 + 1e-5f) * sc[2];
    const float sc1   = rsqrtf(var1 + 1e-5f) * sc[3];
    const float be0   = sc[4], be1 = sc[5];

    float* o0 = out + (b*OCn + 0)*Nn + (r0 + row)*Wn;
    float* o1 = out + (b*OCn + 1)*Nn + (r0 + row)*Wn;
    #pragma unroll
    for (int j = 0; j < 2; j++) {
        const int c = (j == 0) ? colA : colB;
        float v0 = (y0[j] - mean0) * sc0 + be0;
        float v1 = (y1[j] - mean1) * sc1 + be1;
        o0[c] = (v0 >= 0.f) ? v0 : 0.1f*v0;
        o1[c] = (v1 >= 0.f) ? v1 : 0.1f*v1;
    }
}

// ---------------------------------------------------------------------------
extern "C" void kernel_launch(void* const* d_in, const int* in_sizes, int n_in,
                              void* d_out, int out_size)
{
    const float* q      = (const float*)d_in[0];  // X_tnext
    const float* k      = (const float*)d_in[1];  // X_hat_tnext
    const float* conv_w = (const float*)d_in[2];
    const float* conv_b = (const float*)d_in[3];
    const float* gamma  = (const float*)d_in[4];
    const float* beta   = (const float*)d_in[5];
    float* out = (float*)d_out;

    fused_2clu<<<NCTA, NT>>>(q, k, conv_w, conv_b, gamma, beta, out);
}